// round 16
// baseline (speedup 1.0000x reference)
#include <cuda_runtime.h>
#include <cuda_fp16.h>
#include <cstdint>

#define Mm 196

// ---- kernel1 smem offsets ----
#define K1_B      0u        // 8*8*32*8 = 16384 (B fragments, hi only)
#define K1_QS     16384u    // 128 f
#define K1_WS     16896u    // 64 f
#define K1_BB     17152u    // 64 f
#define K1_MASK   17408u    // 256 f zero-padded
#define K1_POOLP  18432u    // 8*64 f = 2048
#define K1_HLOG   20480u    // 128 f (half-local logits)
#define K1_WTS    20992u    // 128 f
#define K1_V2P    21504u    // 8*128 f = 4096 (16B aligned); reused as sred in combine
#define K1_RED    25600u    // 8 f
#define K1_POOL   25632u    // 64 f (combine)
#define K1_FLAG   25888u    // int
#define K1_V2S    25984u    // 56 rows x 512B = 28672 (cp.async staging)
#define K1_SMEM   54656u

#define V2S_ROWS 56

__device__ float g_poolp[2048 * 64];
__device__ float g_S[2048 * 128];
__device__ float g_mz[2048 * 2];
__device__ int   g_cnt[1024];     // zero-init; reset by combiner each run

__device__ __forceinline__ uint32_t pack_hi(float x, float y) {
    __half hx = __float2half_rn(x), hy = __float2half_rn(y);
    return ((uint32_t)__half_as_ushort(hy) << 16) | (uint32_t)__half_as_ushort(hx);
}

__device__ __forceinline__ void mma16816(float* d, uint32_t a0, uint32_t a1, uint32_t a2,
                                         uint32_t a3, uint32_t b0, uint32_t b1) {
    asm volatile(
        "mma.sync.aligned.m16n8k16.row.col.f32.f16.f16.f32 "
        "{%0,%1,%2,%3}, {%4,%5,%6,%7}, {%8,%9}, {%0,%1,%2,%3};"
        : "+f"(d[0]), "+f"(d[1]), "+f"(d[2]), "+f"(d[3])
        : "r"(a0), "r"(a1), "r"(a2), "r"(a3), "r"(b0), "r"(b1));
}

__device__ __forceinline__ void lds64(uint32_t& x, uint32_t& y, uint32_t addr) {
    asm volatile("ld.shared.v2.b32 {%0,%1}, [%2];" : "=r"(x), "=r"(y) : "r"(addr));
}

// ====== single kernel: GEMM + logits + pool + local softmax + weighted v2
// ====== + last-CTA cross-half combine (flash merge + channel gate + output)
__global__ __launch_bounds__(256, 4)
void k1_gemm(const float* __restrict__ qg, const float* __restrict__ keyg_all,
             const float* __restrict__ maskg, const float* __restrict__ Wbg,
             const float* __restrict__ bbg, const float* __restrict__ Wsg,
             const float* __restrict__ v2g_all, const float* __restrict__ v1g,
             const float* __restrict__ Wcg, const float* __restrict__ bcg,
             float* __restrict__ outg)
{
    extern __shared__ char sm[];
    const uint32_t smb = (uint32_t)__cvta_generic_to_shared(sm);
    const int tid = threadIdx.x;
    const int lane = tid & 31;
    const int wid = tid >> 5;
    const int bid = blockIdx.x;
    const int bh = bid >> 1;
    const int half = bid & 1;
    const int b = bh >> 3;
    const int m0 = half * 112;
    const int rows = half ? (Mm - 112) : 112;      // 112 or 84
    const int ntiles = half ? 6 : 7;

    float* qs    = (float*)(sm + K1_QS);
    float* wss   = (float*)(sm + K1_WS);
    float* bbs   = (float*)(sm + K1_BB);
    float* maskv = (float*)(sm + K1_MASK);
    float* poolp = (float*)(sm + K1_POOLP);
    float* hlog  = (float*)(sm + K1_HLOG);
    float* wts   = (float*)(sm + K1_WTS);
    float* v2p   = (float*)(sm + K1_V2P);
    float* red   = (float*)(sm + K1_RED);
    float* pool  = (float*)(sm + K1_POOL);
    int*   flagp = (int*)(sm + K1_FLAG);

    const float* keyg = keyg_all + (size_t)bh * Mm * 128;
    const int g = lane >> 2, t = lane & 3;
    const int r0 = m0 + wid * 16 + g;
    const int r1 = r0 + 8;
    const int r0c = (r0 < Mm) ? r0 : (Mm - 1);
    const int r1c = (r1 < Mm) ? r1 : (Mm - 1);
    const float4* p0 = (const float4*)(keyg + r0c * 128) + t;
    const float4* p1 = (const float4*)(keyg + r1c * 128) + t;

    // prefetch ks=0,1 (A operand)
    float4 P0a, P0b, P1a, P1b;
    if (wid < ntiles) {
        P0a = p0[0]; P1a = p1[0];
        P0b = p0[4]; P1b = p1[4];
    }

    // ---- cp.async prefetch of v2 rows 0..55 of this half into smem ----
    // lands during B-pack + MMA; consumed in the weighted v2 phase.
    const float* v2base = v2g_all + (size_t)bh * Mm * 128 + m0 * 128;
    {
        #pragma unroll
        for (int k = 0; k < 7; ++k) {
            const int c = tid + k * 256;            // 1792 16B-chunks = 56 rows
            const uint32_t saddr = smb + K1_V2S + (uint32_t)c * 16;
            const float* gaddr = v2base + c * 4;
            asm volatile("cp.async.cg.shared.global [%0], [%1], 16;"
                         :: "r"(saddr), "l"(gaddr));
        }
        asm volatile("cp.async.commit_group;");
    }

    if (tid < 128) qs[tid] = qg[bh * 128 + tid];
    if (tid < 64) { wss[tid] = Wsg[tid]; bbs[tid] = bbg[tid]; }
    maskv[tid] = (tid < Mm) ? maskg[b * Mm + tid] : 0.f;
    __syncthreads();

    // pack B fragments (hi only): Wq[k][e] = q[k]*Wb[k][e], k-permuted
    #pragma unroll
    for (int task = tid; task < 512; task += 256) {
        const int e = task & 63;
        const int ks = task >> 6;
        const int nt = e >> 3;
        const uint32_t slotbase = (uint32_t)((nt * 8 + ks) * 32);
        #pragma unroll
        for (int tt = 0; tt < 4; ++tt) {
            const int c = ks * 16 + tt * 4;
            const float x0 = Wbg[c * 64 + e] * qs[c];
            const float x1 = Wbg[(c + 1) * 64 + e] * qs[c + 1];
            const float x2 = Wbg[(c + 2) * 64 + e] * qs[c + 2];
            const float x3 = Wbg[(c + 3) * 64 + e] * qs[c + 3];
            uint2 val;
            val.x = pack_hi(x0, x1);
            val.y = pack_hi(x2, x3);
            const int ln = 4 * (e & 7) + tt;
            *(uint2*)(sm + K1_B + (slotbase + ln) * 8) = val;
        }
    }
    __syncthreads();

    if (wid < ntiles) {
        float acc[8][4];
        #pragma unroll
        for (int nt = 0; nt < 8; ++nt)
            #pragma unroll
            for (int r = 0; r < 4; ++r) acc[nt][r] = 0.f;

        #pragma unroll
        for (int ks = 0; ks < 8; ++ks) {
            const float4 c0 = (ks & 1) ? P0b : P0a;
            const float4 c1 = (ks & 1) ? P1b : P1a;
            if (ks < 6) {
                if (ks & 1) { P0b = p0[(ks + 2) * 4]; P1b = p1[(ks + 2) * 4]; }
                else        { P0a = p0[(ks + 2) * 4]; P1a = p1[(ks + 2) * 4]; }
            }
            const uint32_t a0 = pack_hi(c0.x, c0.y);
            const uint32_t a1 = pack_hi(c1.x, c1.y);
            const uint32_t a2 = pack_hi(c0.z, c0.w);
            const uint32_t a3 = pack_hi(c1.z, c1.w);
            #pragma unroll
            for (int nt = 0; nt < 8; ++nt) {
                uint32_t b0h, b1h;
                lds64(b0h, b1h,
                      smb + K1_B + (uint32_t)((nt * 8 + ks) * 32 + lane) * 8);
                mma16816(acc[nt], a0, a1, a2, a3, b0h, b1h);
            }
        }

        const float mk0 = maskv[r0 < 256 ? r0 : 255];
        const float mk1 = maskv[r1 < 256 ? r1 : 255];
        float lp0 = 0.f, lp1 = 0.f;
        #pragma unroll
        for (int nt = 0; nt < 8; ++nt) {
            const int e0 = nt * 8 + t * 2;
            const float ba = bbs[e0], bbv = bbs[e0 + 1];
            const float wa = wss[e0], wbv = wss[e0 + 1];
            float h0 = fmaxf(acc[nt][0] + ba, 0.f);
            float h1 = fmaxf(acc[nt][1] + bbv, 0.f);
            float h2 = fmaxf(acc[nt][2] + ba, 0.f);
            float h3 = fmaxf(acc[nt][3] + bbv, 0.f);
            lp0 += h0 * wa + h1 * wbv;
            lp1 += h2 * wa + h3 * wbv;
            float pva = mk0 * h0 + mk1 * h2;
            float pvb = mk0 * h1 + mk1 * h3;
            pva += __shfl_xor_sync(0xffffffffu, pva, 4);
            pva += __shfl_xor_sync(0xffffffffu, pva, 8);
            pva += __shfl_xor_sync(0xffffffffu, pva, 16);
            pvb += __shfl_xor_sync(0xffffffffu, pvb, 4);
            pvb += __shfl_xor_sync(0xffffffffu, pvb, 8);
            pvb += __shfl_xor_sync(0xffffffffu, pvb, 16);
            if (g == 0) {
                poolp[wid * 64 + e0] = pva;
                poolp[wid * 64 + e0 + 1] = pvb;
            }
        }
        lp0 += __shfl_xor_sync(0xffffffffu, lp0, 1);
        lp0 += __shfl_xor_sync(0xffffffffu, lp0, 2);
        lp1 += __shfl_xor_sync(0xffffffffu, lp1, 1);
        lp1 += __shfl_xor_sync(0xffffffffu, lp1, 2);
        if (t == 0) {
            if (r0 < Mm) hlog[r0 - m0] = lp0;
            if (r1 < Mm) hlog[r1 - m0] = lp1;
        }
    }
    __syncthreads();

    // pool partial to global
    if (tid < 64) {
        float s = 0.f;
        for (int w = 0; w < ntiles; ++w) s += poolp[w * 64 + tid];
        g_poolp[bid * 64 + tid] = s;
    }

    // ---- local (half) softmax: m_l, Z_l, wts ----
    float lv = -1e30f;
    if (tid < rows) lv = (maskv[m0 + tid] == 0.f) ? -1e9f : hlog[tid];

    float v = lv;
    #pragma unroll
    for (int off = 16; off > 0; off >>= 1) v = fmaxf(v, __shfl_xor_sync(0xffffffffu, v, off));
    if (lane == 0) red[wid] = v;
    __syncthreads();
    float ml = red[0];
    #pragma unroll
    for (int i = 1; i < 8; ++i) ml = fmaxf(ml, red[i]);
    __syncthreads();

    float w = (tid < rows) ? __expf(lv - ml) : 0.f;
    if (tid < rows) wts[tid] = w;
    float sw = w;
    #pragma unroll
    for (int off = 16; off > 0; off >>= 1) sw += __shfl_xor_sync(0xffffffffu, sw, off);
    if (lane == 0) red[wid] = sw;
    __syncthreads();
    float Zl = 0.f;
    #pragma unroll
    for (int i = 0; i < 8; ++i) Zl += red[i];

    // ---- weighted v2 partial: rows 0..55 from smem (cp.async), rest from global ----
    asm volatile("cp.async.wait_group 0;" ::: "memory");
    __syncthreads();

    const float4* v2r = (const float4*)v2base;
    float4 a4 = make_float4(0.f, 0.f, 0.f, 0.f);
    #pragma unroll
    for (int i = 0; i < 7; ++i) {                   // rows wid, wid+8, ..., wid+48 < 56
        const int mr = wid + 8 * i;
        const float wt = wts[mr];
        const float4 vv = *(const float4*)(sm + K1_V2S + (uint32_t)(mr * 32 + lane) * 16);
        a4.x += wt * vv.x;
        a4.y += wt * vv.y;
        a4.z += wt * vv.z;
        a4.w += wt * vv.w;
    }
    #pragma unroll
    for (int i = 7; i < 14; ++i) {                  // rows 56..111 (guarded)
        const int mr = wid + 8 * i;
        if (mr < rows) {
            const float wt = wts[mr];
            const float4 vv = v2r[mr * 32 + lane];
            a4.x += wt * vv.x;
            a4.y += wt * vv.y;
            a4.z += wt * vv.z;
            a4.w += wt * vv.w;
        }
    }
    *(float4*)(sm + K1_V2P + (uint32_t)(wid * 32 + lane) * 16) = a4;
    __syncthreads();

    if (tid < 128) {
        float s = 0.f;
        #pragma unroll
        for (int gg = 0; gg < 8; ++gg) s += v2p[gg * 128 + tid];
        g_S[bid * 128 + tid] = s;
    }
    if (tid == 128) { g_mz[bid * 2] = ml; g_mz[bid * 2 + 1] = Zl; }

    // ---- last-CTA-done combine ----
    __threadfence();
    __syncthreads();
    if (tid == 0) {
        const int old = atomicAdd(&g_cnt[bh], 1);
        *flagp = (old == 1);
    }
    __syncthreads();

    if (*flagp) {
        // mask count (deterministic block reduce over full mask in smem)
        float mv = maskv[tid];
        #pragma unroll
        for (int off = 16; off > 0; off >>= 1) mv += __shfl_xor_sync(0xffffffffu, mv, off);
        if (lane == 0) red[wid] = mv;
        __syncthreads();
        float cn = 0.f;
        #pragma unroll
        for (int i = 0; i < 8; ++i) cn += red[i];

        if (tid < 64)
            pool[tid] = (__ldcg(&g_poolp[(bh * 2) * 64 + tid]) +
                         __ldcg(&g_poolp[(bh * 2 + 1) * 64 + tid])) / cn;
        __syncthreads();

        // gate dot split: threads tid<128 do e 0..31 of channel tid; tid>=128 do e 32..63
        {
            const int vv = tid & 127;
            const int hseg = tid >> 7;
            float s = 0.f;
            const int e0 = hseg * 32;
            #pragma unroll 8
            for (int e = 0; e < 32; ++e)
                s += pool[e0 + e] * Wcg[(e0 + e) * 128 + vv];
            v2p[hseg * 128 + vv] = s;   // reuse v2p smem as sred
        }
        __syncthreads();

        if (tid < 128) {
            const float m0v = __ldcg(&g_mz[(bh * 2) * 2]);
            const float Z0  = __ldcg(&g_mz[(bh * 2) * 2 + 1]);
            const float m1v = __ldcg(&g_mz[(bh * 2 + 1) * 2]);
            const float Z1  = __ldcg(&g_mz[(bh * 2 + 1) * 2 + 1]);
            const float M = fmaxf(m0v, m1v);
            const float w0 = __expf(m0v - M), w1 = __expf(m1v - M);
            const float v2v = (__ldcg(&g_S[(bh * 2) * 128 + tid]) * w0 +
                               __ldcg(&g_S[(bh * 2 + 1) * 128 + tid]) * w1)
                            / (Z0 * w0 + Z1 * w1);
            const float s = v2p[tid] + v2p[128 + tid];
            const float ac = 1.f / (1.f + __expf(-(s + bcg[tid])));
            outg[bh * 128 + tid] = v1g[bh * 128 + tid] * v2v * ac;
        }
        __syncthreads();
        if (tid == 0) g_cnt[bh] = 0;    // reset for next graph replay
    }
}

extern "C" void kernel_launch(void* const* d_in, const int* in_sizes, int n_in,
                              void* d_out, int out_size) {
    const float* q   = (const float*)d_in[0];
    const float* key = (const float*)d_in[1];
    const float* msk = (const float*)d_in[2];
    const float* v1  = (const float*)d_in[3];
    const float* v2  = (const float*)d_in[4];
    const float* Wb  = (const float*)d_in[5];
    const float* bb  = (const float*)d_in[6];
    const float* Ws  = (const float*)d_in[7];
    const float* Wc  = (const float*)d_in[9];
    const float* bc  = (const float*)d_in[10];
    float* out = (float*)d_out;

    cudaFuncSetAttribute(k1_gemm, cudaFuncAttributeMaxDynamicSharedMemorySize, (int)K1_SMEM);
    k1_gemm<<<2048, 256, K1_SMEM>>>(q, key, msk, Wb, bb, Ws, v2, v1, Wc, bc, out);
}

// round 17
// speedup vs baseline: 1.1676x; 1.1676x over previous
#include <cuda_runtime.h>
#include <cuda_fp16.h>
#include <cstdint>

#define Mm 196

// ---- kernel1 smem offsets ----
#define K1_B      0u        // 8*8*32*8 = 16384 (B fragments, hi only)
#define K1_QS     16384u    // 128 f
#define K1_WS     16896u    // 64 f
#define K1_BB     17152u    // 64 f
#define K1_MASK   17408u    // 256 f zero-padded
#define K1_POOLP  18432u    // 8*64 f = 2048
#define K1_HLOG   20480u    // 128 f (half-local logits)
#define K1_WTS    20992u    // 128 f
#define K1_V2P    21504u    // 8*128 f = 4096 (16B aligned); reused as sred in combine
#define K1_RED    25600u    // 8 f
#define K1_POOL   25632u    // 64 f (combine)
#define K1_FLAG   25888u    // int
#define K1_SMEM   25892u

__device__ float g_poolp[2048 * 64];
__device__ float g_S[2048 * 128];
__device__ float g_mz[2048 * 2];
__device__ int   g_cnt[1024];     // zero-init; reset by combiner each run

__device__ __forceinline__ uint32_t pack_hi(float x, float y) {
    __half hx = __float2half_rn(x), hy = __float2half_rn(y);
    return ((uint32_t)__half_as_ushort(hy) << 16) | (uint32_t)__half_as_ushort(hx);
}

__device__ __forceinline__ void mma16816(float* d, uint32_t a0, uint32_t a1, uint32_t a2,
                                         uint32_t a3, uint32_t b0, uint32_t b1) {
    asm volatile(
        "mma.sync.aligned.m16n8k16.row.col.f32.f16.f16.f32 "
        "{%0,%1,%2,%3}, {%4,%5,%6,%7}, {%8,%9}, {%0,%1,%2,%3};"
        : "+f"(d[0]), "+f"(d[1]), "+f"(d[2]), "+f"(d[3])
        : "r"(a0), "r"(a1), "r"(a2), "r"(a3), "r"(b0), "r"(b1));
}

__device__ __forceinline__ void lds64(uint32_t& x, uint32_t& y, uint32_t addr) {
    asm volatile("ld.shared.v2.b32 {%0,%1}, [%2];" : "=r"(x), "=r"(y) : "r"(addr));
}

__device__ __forceinline__ float4 ldcs4(const float4* p) {
    float4 v;
    asm volatile("ld.global.cs.v4.f32 {%0,%1,%2,%3}, [%4];"
                 : "=f"(v.x), "=f"(v.y), "=f"(v.z), "=f"(v.w) : "l"(p));
    return v;
}

// ====== single kernel: GEMM + logits + pool + local softmax + weighted v2
// ====== + last-CTA cross-half combine (flash merge + channel gate + output)
__global__ __launch_bounds__(256, 4)
void k1_gemm(const float* __restrict__ qg, const float* __restrict__ keyg_all,
             const float* __restrict__ maskg, const float* __restrict__ Wbg,
             const float* __restrict__ bbg, const float* __restrict__ Wsg,
             const float* __restrict__ v2g_all, const float* __restrict__ v1g,
             const float* __restrict__ Wcg, const float* __restrict__ bcg,
             float* __restrict__ outg)
{
    extern __shared__ char sm[];
    const uint32_t smb = (uint32_t)__cvta_generic_to_shared(sm);
    const int tid = threadIdx.x;
    const int lane = tid & 31;
    const int wid = tid >> 5;
    const int bid = blockIdx.x;
    const int bh = bid >> 1;
    const int half = bid & 1;
    const int b = bh >> 3;
    const int m0 = half * 112;
    const int rows = half ? (Mm - 112) : 112;      // 112 or 84
    const int ntiles = half ? 6 : 7;

    float* qs    = (float*)(sm + K1_QS);
    float* wss   = (float*)(sm + K1_WS);
    float* bbs   = (float*)(sm + K1_BB);
    float* maskv = (float*)(sm + K1_MASK);
    float* poolp = (float*)(sm + K1_POOLP);
    float* hlog  = (float*)(sm + K1_HLOG);
    float* wts   = (float*)(sm + K1_WTS);
    float* v2p   = (float*)(sm + K1_V2P);
    float* red   = (float*)(sm + K1_RED);
    float* pool  = (float*)(sm + K1_POOL);
    int*   flagp = (int*)(sm + K1_FLAG);

    const float* keyg = keyg_all + (size_t)bh * Mm * 128;
    const int g = lane >> 2, t = lane & 3;
    const int r0 = m0 + wid * 16 + g;
    const int r1 = r0 + 8;
    const int r0c = (r0 < Mm) ? r0 : (Mm - 1);
    const int r1c = (r1 < Mm) ? r1 : (Mm - 1);
    const float4* p0 = (const float4*)(keyg + r0c * 128) + t;
    const float4* p1 = (const float4*)(keyg + r1c * 128) + t;

    // prefetch ks=0,1 (A operand, streaming)
    float4 P0a, P0b, P1a, P1b;
    if (wid < ntiles) {
        P0a = ldcs4(p0);     P1a = ldcs4(p1);
        P0b = ldcs4(p0 + 4); P1b = ldcs4(p1 + 4);
    }

    if (tid < 128) qs[tid] = qg[bh * 128 + tid];
    if (tid < 64) { wss[tid] = Wsg[tid]; bbs[tid] = bbg[tid]; }
    maskv[tid] = (tid < Mm) ? maskg[b * Mm + tid] : 0.f;
    __syncthreads();

    // pack B fragments (hi only): Wq[k][e] = q[k]*Wb[k][e], k-permuted
    #pragma unroll
    for (int task = tid; task < 512; task += 256) {
        const int e = task & 63;
        const int ks = task >> 6;
        const int nt = e >> 3;
        const uint32_t slotbase = (uint32_t)((nt * 8 + ks) * 32);
        #pragma unroll
        for (int tt = 0; tt < 4; ++tt) {
            const int c = ks * 16 + tt * 4;
            const float x0 = Wbg[c * 64 + e] * qs[c];
            const float x1 = Wbg[(c + 1) * 64 + e] * qs[c + 1];
            const float x2 = Wbg[(c + 2) * 64 + e] * qs[c + 2];
            const float x3 = Wbg[(c + 3) * 64 + e] * qs[c + 3];
            uint2 val;
            val.x = pack_hi(x0, x1);
            val.y = pack_hi(x2, x3);
            const int ln = 4 * (e & 7) + tt;
            *(uint2*)(sm + K1_B + (slotbase + ln) * 8) = val;
        }
    }
    __syncthreads();

    if (wid < ntiles) {
        float acc[8][4];
        #pragma unroll
        for (int nt = 0; nt < 8; ++nt)
            #pragma unroll
            for (int r = 0; r < 4; ++r) acc[nt][r] = 0.f;

        #pragma unroll
        for (int ks = 0; ks < 8; ++ks) {
            const float4 c0 = (ks & 1) ? P0b : P0a;
            const float4 c1 = (ks & 1) ? P1b : P1a;
            if (ks < 6) {
                if (ks & 1) { P0b = ldcs4(p0 + (ks + 2) * 4); P1b = ldcs4(p1 + (ks + 2) * 4); }
                else        { P0a = ldcs4(p0 + (ks + 2) * 4); P1a = ldcs4(p1 + (ks + 2) * 4); }
            }
            const uint32_t a0 = pack_hi(c0.x, c0.y);
            const uint32_t a1 = pack_hi(c1.x, c1.y);
            const uint32_t a2 = pack_hi(c0.z, c0.w);
            const uint32_t a3 = pack_hi(c1.z, c1.w);
            #pragma unroll
            for (int nt = 0; nt < 8; ++nt) {
                uint32_t b0h, b1h;
                lds64(b0h, b1h,
                      smb + K1_B + (uint32_t)((nt * 8 + ks) * 32 + lane) * 8);
                mma16816(acc[nt], a0, a1, a2, a3, b0h, b1h);
            }
        }

        const float mk0 = maskv[r0 < 256 ? r0 : 255];
        const float mk1 = maskv[r1 < 256 ? r1 : 255];
        float lp0 = 0.f, lp1 = 0.f;
        #pragma unroll
        for (int nt = 0; nt < 8; ++nt) {
            const int e0 = nt * 8 + t * 2;
            const float ba = bbs[e0], bbv = bbs[e0 + 1];
            const float wa = wss[e0], wbv = wss[e0 + 1];
            float h0 = fmaxf(acc[nt][0] + ba, 0.f);
            float h1 = fmaxf(acc[nt][1] + bbv, 0.f);
            float h2 = fmaxf(acc[nt][2] + ba, 0.f);
            float h3 = fmaxf(acc[nt][3] + bbv, 0.f);
            lp0 += h0 * wa + h1 * wbv;
            lp1 += h2 * wa + h3 * wbv;
            float pva = mk0 * h0 + mk1 * h2;
            float pvb = mk0 * h1 + mk1 * h3;
            pva += __shfl_xor_sync(0xffffffffu, pva, 4);
            pva += __shfl_xor_sync(0xffffffffu, pva, 8);
            pva += __shfl_xor_sync(0xffffffffu, pva, 16);
            pvb += __shfl_xor_sync(0xffffffffu, pvb, 4);
            pvb += __shfl_xor_sync(0xffffffffu, pvb, 8);
            pvb += __shfl_xor_sync(0xffffffffu, pvb, 16);
            if (g == 0) {
                poolp[wid * 64 + e0] = pva;
                poolp[wid * 64 + e0 + 1] = pvb;
            }
        }
        lp0 += __shfl_xor_sync(0xffffffffu, lp0, 1);
        lp0 += __shfl_xor_sync(0xffffffffu, lp0, 2);
        lp1 += __shfl_xor_sync(0xffffffffu, lp1, 1);
        lp1 += __shfl_xor_sync(0xffffffffu, lp1, 2);
        if (t == 0) {
            if (r0 < Mm) hlog[r0 - m0] = lp0;
            if (r1 < Mm) hlog[r1 - m0] = lp1;
        }
    }
    __syncthreads();

    // pool partial to global
    if (tid < 64) {
        float s = 0.f;
        for (int w = 0; w < ntiles; ++w) s += poolp[w * 64 + tid];
        g_poolp[bid * 64 + tid] = s;
    }

    // ---- issue first two v2 loads NOW (independent of softmax) ----
    const float4* v2r = (const float4*)(v2g_all + (size_t)bh * Mm * 128) + m0 * 32;
    float4 V0 = ldcs4(v2r + (wid) * 32 + lane);          // row wid (<84 always)
    float4 V1 = ldcs4(v2r + (wid + 8) * 32 + lane);      // row wid+8 (<84 always)

    // ---- local (half) softmax: m_l, Z_l, wts ----
    float lv = -1e30f;
    if (tid < rows) lv = (maskv[m0 + tid] == 0.f) ? -1e9f : hlog[tid];

    float v = lv;
    #pragma unroll
    for (int off = 16; off > 0; off >>= 1) v = fmaxf(v, __shfl_xor_sync(0xffffffffu, v, off));
    if (lane == 0) red[wid] = v;
    __syncthreads();
    float ml = red[0];
    #pragma unroll
    for (int i = 1; i < 8; ++i) ml = fmaxf(ml, red[i]);
    __syncthreads();

    float w = (tid < rows) ? __expf(lv - ml) : 0.f;
    if (tid < rows) wts[tid] = w;
    float sw = w;
    #pragma unroll
    for (int off = 16; off > 0; off >>= 1) sw += __shfl_xor_sync(0xffffffffu, sw, off);
    if (lane == 0) red[wid] = sw;
    __syncthreads();
    float Zl = 0.f;
    #pragma unroll
    for (int i = 0; i < 8; ++i) Zl += red[i];

    // ---- weighted v2 partial over this half's rows ----
    float4 a4;
    {
        const float w0v = wts[wid];
        const float w1v = wts[wid + 8];
        a4.x = w0v * V0.x + w1v * V1.x;
        a4.y = w0v * V0.y + w1v * V1.y;
        a4.z = w0v * V0.z + w1v * V1.z;
        a4.w = w0v * V0.w + w1v * V1.w;
    }
    #pragma unroll
    for (int i = 2; i < 14; ++i) {
        const int mr = wid + 8 * i;
        if (mr < rows) {
            const float wt = wts[mr];
            const float4 vv = ldcs4(v2r + mr * 32 + lane);
            a4.x += wt * vv.x;
            a4.y += wt * vv.y;
            a4.z += wt * vv.z;
            a4.w += wt * vv.w;
        }
    }
    *(float4*)(sm + K1_V2P + (uint32_t)(wid * 32 + lane) * 16) = a4;
    __syncthreads();

    if (tid < 128) {
        float s = 0.f;
        #pragma unroll
        for (int gg = 0; gg < 8; ++gg) s += v2p[gg * 128 + tid];
        g_S[bid * 128 + tid] = s;
    }
    if (tid == 128) { g_mz[bid * 2] = ml; g_mz[bid * 2 + 1] = Zl; }

    // ---- last-CTA-done combine ----
    __threadfence();
    __syncthreads();
    if (tid == 0) {
        const int old = atomicAdd(&g_cnt[bh], 1);
        *flagp = (old == 1);
    }
    __syncthreads();

    if (*flagp) {
        // mask count (deterministic block reduce over full mask in smem)
        float mv = maskv[tid];
        #pragma unroll
        for (int off = 16; off > 0; off >>= 1) mv += __shfl_xor_sync(0xffffffffu, mv, off);
        if (lane == 0) red[wid] = mv;
        __syncthreads();
        float cn = 0.f;
        #pragma unroll
        for (int i = 0; i < 8; ++i) cn += red[i];

        if (tid < 64)
            pool[tid] = (__ldcg(&g_poolp[(bh * 2) * 64 + tid]) +
                         __ldcg(&g_poolp[(bh * 2 + 1) * 64 + tid])) / cn;
        __syncthreads();

        // gate dot split: threads tid<128 do e 0..31 of channel tid; tid>=128 do e 32..63
        {
            const int vv = tid & 127;
            const int hseg = tid >> 7;
            float s = 0.f;
            const int e0 = hseg * 32;
            #pragma unroll 8
            for (int e = 0; e < 32; ++e)
                s += pool[e0 + e] * Wcg[(e0 + e) * 128 + vv];
            v2p[hseg * 128 + vv] = s;   // reuse v2p smem as sred
        }
        __syncthreads();

        if (tid < 128) {
            const float m0v = __ldcg(&g_mz[(bh * 2) * 2]);
            const float Z0  = __ldcg(&g_mz[(bh * 2) * 2 + 1]);
            const float m1v = __ldcg(&g_mz[(bh * 2 + 1) * 2]);
            const float Z1  = __ldcg(&g_mz[(bh * 2 + 1) * 2 + 1]);
            const float M = fmaxf(m0v, m1v);
            const float w0 = __expf(m0v - M), w1 = __expf(m1v - M);
            const float v2v = (__ldcg(&g_S[(bh * 2) * 128 + tid]) * w0 +
                               __ldcg(&g_S[(bh * 2 + 1) * 128 + tid]) * w1)
                            / (Z0 * w0 + Z1 * w1);
            const float s = v2p[tid] + v2p[128 + tid];
            const float ac = 1.f / (1.f + __expf(-(s + bcg[tid])));
            outg[bh * 128 + tid] = v1g[bh * 128 + tid] * v2v * ac;
        }
        __syncthreads();
        if (tid == 0) g_cnt[bh] = 0;    // reset for next graph replay
    }
}

extern "C" void kernel_launch(void* const* d_in, const int* in_sizes, int n_in,
                              void* d_out, int out_size) {
    const float* q   = (const float*)d_in[0];
    const float* key = (const float*)d_in[1];
    const float* msk = (const float*)d_in[2];
    const float* v1  = (const float*)d_in[3];
    const float* v2  = (const float*)d_in[4];
    const float* Wb  = (const float*)d_in[5];
    const float* bb  = (const float*)d_in[6];
    const float* Ws  = (const float*)d_in[7];
    const float* Wc  = (const float*)d_in[9];
    const float* bc  = (const float*)d_in[10];
    float* out = (float*)d_out;

    cudaFuncSetAttribute(k1_gemm, cudaFuncAttributeMaxDynamicSharedMemorySize, (int)K1_SMEM);
    k1_gemm<<<2048, 256, K1_SMEM>>>(q, key, msk, Wb, bb, Ws, v2, v1, Wc, bc, out);
}